// round 16
// baseline (speedup 1.0000x reference)
#include <cuda_runtime.h>
#include <cuda_fp16.h>
#include <cstdint>

// ---------------------------------------------------------------------------
// Problem constants
// ---------------------------------------------------------------------------
#define STEPS 128
#define BATCH 256
#define D1 1024
#define D2 1024
#define M_ROWS (127 * BATCH)        // 32512
#define PLANE (BATCH * D2)          // 262144
#define PLANE2 (PLANE / 2)
#define TOTAL2 (STEPS * PLANE2)

#define LSCALE 2048.0f              // 2^11 lo-limb scaling (kills subnormals)
#define LINV   (1.0f / 2048.0f)

// GEMM tiling: CTA 128(M) x 64(N), K-chunk 64, 256 threads (8 warps 4x2),
// 2-stage pipeline, 2 CTAs per SM.  (Best-measured config: R10/R15, 682.5 us.)
#define KC 64
#define NCH 16                      // 1024 / 64 chunks
#define ROWH 72                     // 64 data halfs + 8 pad
#define TA_H (128 * ROWH)           // 9216 halfs per A limb tile
#define TB_H (64 * ROWH)            // 4608 halfs per W limb tile
#define WOFF_H (2 * TA_H)           // W tiles after the 2 A tiles
#define STAGE_H (2 * TA_H + 2 * TB_H)  // 27648 halfs
#define STAGE_B (STAGE_H * 2)       // 55296 bytes
#define SMEM_BYTES (2 * STAGE_B)    // 110592 bytes -> 2 CTAs/SM

// ---------------------------------------------------------------------------
// Device scratch
// ---------------------------------------------------------------------------
__device__ float  g_lin[(size_t)M_ROWS * D2];     // 133 MB
__device__ __half g_A[2][(size_t)M_ROWS * D1];    // 2 x 66.6 MB
__device__ __half g_W[2][(size_t)D2 * D1];        // 2 x 2 MB

// ---------------------------------------------------------------------------
// 2-limb fp16 split with scaled lo: x ~= h + l*2^-11,  l = f16((x-h)*2^11)
// ---------------------------------------------------------------------------
__global__ __launch_bounds__(256) void split2(const float* __restrict__ src,
                                              __half* __restrict__ oh,
                                              __half* __restrict__ ol, int n8) {
    int i = blockIdx.x * blockDim.x + threadIdx.x;
    if (i >= n8) return;
    const float4* s = (const float4*)(src + (size_t)i * 8);
    float4 v0 = s[0], v1 = s[1];
    float x[8] = {v0.x, v0.y, v0.z, v0.w, v1.x, v1.y, v1.z, v1.w};
    unsigned short h[8], l[8];
#pragma unroll
    for (int q = 0; q < 8; q++) {
        __half a = __float2half_rn(x[q]);
        float r = (x[q] - __half2float(a)) * LSCALE;
        h[q] = __half_as_ushort(a);
        l[q] = __half_as_ushort(__float2half_rn(r));
    }
    uint4 p;
    p.x = h[0] | ((uint32_t)h[1] << 16); p.y = h[2] | ((uint32_t)h[3] << 16);
    p.z = h[4] | ((uint32_t)h[5] << 16); p.w = h[6] | ((uint32_t)h[7] << 16);
    ((uint4*)oh)[i] = p;
    p.x = l[0] | ((uint32_t)l[1] << 16); p.y = l[2] | ((uint32_t)l[3] << 16);
    p.z = l[4] | ((uint32_t)l[5] << 16); p.w = l[6] | ((uint32_t)l[7] << 16);
    ((uint4*)ol)[i] = p;
}

// ---------------------------------------------------------------------------
// MMA / ldmatrix helpers (fp16, fp32 accumulate)
// ---------------------------------------------------------------------------
__device__ __forceinline__ void ldm4(uint32_t* r, uint32_t a) {
    asm volatile("ldmatrix.sync.aligned.m8n8.x4.shared.b16 {%0,%1,%2,%3}, [%4];"
        : "=r"(r[0]), "=r"(r[1]), "=r"(r[2]), "=r"(r[3]) : "r"(a));
}
__device__ __forceinline__ void mma_acc(float* c, const uint32_t* a, const uint32_t* b) {
    asm volatile(
        "mma.sync.aligned.m16n8k16.row.col.f32.f16.f16.f32 "
        "{%0,%1,%2,%3}, {%4,%5,%6,%7}, {%8,%9}, {%0,%1,%2,%3};"
        : "+f"(c[0]), "+f"(c[1]), "+f"(c[2]), "+f"(c[3])
        : "r"(a[0]), "r"(a[1]), "r"(a[2]), "r"(a[3]), "r"(b[0]), "r"(b[1]));
}
__device__ __forceinline__ void mma_zro(float* d, const uint32_t* a, const uint32_t* b) {
    asm volatile(
        "mma.sync.aligned.m16n8k16.row.col.f32.f16.f16.f32 "
        "{%0,%1,%2,%3}, {%4,%5,%6,%7}, {%8,%9}, {%10,%10,%10,%10};"
        : "=f"(d[0]), "=f"(d[1]), "=f"(d[2]), "=f"(d[3])
        : "r"(a[0]), "r"(a[1]), "r"(a[2]), "r"(a[3]), "r"(b[0]), "r"(b[1]),
          "f"(0.0f));
}

// ---------------------------------------------------------------------------
// GEMM: lin = A @ W^T via 3 fp16 limb products.
// hh: chain length 2 (one k32 pair per fresh chain) then RN FADD into ct --
// empirically-validated anti-RZ scheme. Cross (h*l' + l'*h): chained in al at
// 2^11 scale; ct += al * 2^-11 at the end. ll dropped (<= 2^-24 relative).
// CTA 128x64, 256 thr, 2-stage cp.async pipeline (2-barrier schedule),
// 2 CTAs/SM so one CTA's HMMAs cover the other's barrier drains.
// ---------------------------------------------------------------------------
__global__ __launch_bounds__(256, 2) void gemm_limb_kernel() {
    extern __shared__ __half smp[];
    const int tid = threadIdx.x, lane = tid & 31, wid = tid >> 5;
    const int wm = wid & 3, wn = wid >> 2;       // 4(M) x 2(N) warp grid
    const int r4 = lane >> 2, cq = lane & 3;
    const int nb = blockIdx.x, mb = blockIdx.y;
    const int m0 = mb * 128, n0 = nb * 64;
    uint32_t smem_base = (uint32_t)__cvta_generic_to_shared(smp);

    float ct[2][4][4], al[2][4][4];
#pragma unroll
    for (int im = 0; im < 2; im++)
#pragma unroll
        for (int jn = 0; jn < 4; jn++)
#pragma unroll
            for (int q = 0; q < 4; q++) { ct[im][jn][q] = 0.f; al[im][jn][q] = 0.f; }

    const __half* Ab = &g_A[0][0] + (size_t)m0 * D1;
    const __half* Wb = &g_W[0][0] + (size_t)n0 * D1;
    const size_t APL = (size_t)M_ROWS * D1;
    const size_t WPL = (size_t)D2 * D1;

    // fill one stage: A 2x128 rows + W 2x64 rows, 8x16B per row -> 3072 chunks
    auto fill = [&](int buf, int kc) {
        int k0 = kc * KC;
        uint32_t sb = smem_base + (uint32_t)buf * STAGE_B;
#pragma unroll
        for (int i = 0; i < 8; i++) {            // A: 2048 chunks
            int ch = i * 256 + tid;
            int tile = ch >> 10;                 // 0=Ah 1=Al
            int r = (ch >> 3) & 127;
            int q = ch & 7;
            const void* src = Ab + (size_t)tile * APL + (size_t)r * D1 + k0 + q * 8;
            uint32_t dst = sb + (uint32_t)(tile * TA_H + r * ROWH + q * 8) * 2;
            asm volatile("cp.async.cg.shared.global [%0], [%1], 16;" :: "r"(dst), "l"(src));
        }
#pragma unroll
        for (int i = 0; i < 4; i++) {            // W: 1024 chunks
            int ch = i * 256 + tid;
            int tile = ch >> 9;                  // 0=Wh 1=Wl
            int r = (ch >> 3) & 63;
            int q = ch & 7;
            const void* src = Wb + (size_t)tile * WPL + (size_t)r * D1 + k0 + q * 8;
            uint32_t dst = sb + (uint32_t)(WOFF_H + tile * TB_H + r * ROWH + q * 8) * 2;
            asm volatile("cp.async.cg.shared.global [%0], [%1], 16;" :: "r"(dst), "l"(src));
        }
        asm volatile("cp.async.commit_group;");
    };

    fill(0, 0);
    fill(1, 1);

    // ldmatrix per-lane address components (halfs) — verified mapping
    const int aRow = wm * 32 + (lane & 15);
    const int aK   = (lane >> 4) * 8;
    const int bRow = wn * 32 + (lane >> 4) * 8 + (lane & 7);
    const int bK   = ((lane >> 3) & 1) * 8;

    for (int s = 0; s < NCH; s++) {
        // fill(s) must be complete: pending groups are fill(s), fill(s+1)
        if (s < NCH - 1) asm volatile("cp.async.wait_group 1;");
        else             asm volatile("cp.async.wait_group 0;");
        __syncthreads();                          // make fill(s) visible to all

        uint32_t sb = smem_base + (uint32_t)(s & 1) * STAGE_B;
#pragma unroll
        for (int kp = 0; kp < 2; kp++) {          // pairs of k16 steps
            uint32_t a0[2][2][4];                 // [ks][im]
            uint32_t b0[2][4][2];                 // [ks][jn]
#pragma unroll
            for (int ks = 0; ks < 2; ks++) {
                int ksub = kp * 2 + ks;
#pragma unroll
                for (int im = 0; im < 2; im++) {
                    uint32_t ad = sb + (uint32_t)((aRow + im * 16) * ROWH
                                   + ksub * 16 + aK) * 2;
                    ldm4(a0[ks][im], ad);
                }
                {
                    uint32_t bd = sb + (uint32_t)(WOFF_H
                                   + bRow * ROWH + ksub * 16 + bK) * 2;
                    uint32_t t[4];
                    ldm4(t, bd);
                    b0[ks][0][0] = t[0]; b0[ks][0][1] = t[1];
                    b0[ks][1][0] = t[2]; b0[ks][1][1] = t[3];
                    bd = sb + (uint32_t)(WOFF_H
                         + (bRow + 16) * ROWH + ksub * 16 + bK) * 2;
                    ldm4(t, bd);
                    b0[ks][2][0] = t[0]; b0[ks][2][1] = t[1];
                    b0[ks][3][0] = t[2]; b0[ks][3][1] = t[3];
                }
            }
            // hh: fresh chain over the k32 pair, then RN dump
#pragma unroll
            for (int im = 0; im < 2; im++)
#pragma unroll
                for (int jn = 0; jn < 4; jn++) {
                    float t4[4];
                    mma_zro(t4, a0[0][im], b0[0][jn]);
                    mma_acc(t4, a0[1][im], b0[1][jn]);
#pragma unroll
                    for (int q = 0; q < 4; q++) ct[im][jn][q] += t4[q];
                }
            // cross terms per k16 (lo-limb frags transient)
#pragma unroll
            for (int ks = 0; ks < 2; ks++) {
                int ksub = kp * 2 + ks;
                uint32_t a1[2][4], b1[4][2];
#pragma unroll
                for (int im = 0; im < 2; im++) {
                    uint32_t ad = sb + (uint32_t)(TA_H + (aRow + im * 16) * ROWH
                                   + ksub * 16 + aK) * 2;
                    ldm4(a1[im], ad);
                }
                {
                    uint32_t bd = sb + (uint32_t)(WOFF_H + TB_H
                                   + bRow * ROWH + ksub * 16 + bK) * 2;
                    uint32_t t[4];
                    ldm4(t, bd);
                    b1[0][0] = t[0]; b1[0][1] = t[1];
                    b1[1][0] = t[2]; b1[1][1] = t[3];
                    bd = sb + (uint32_t)(WOFF_H + TB_H
                         + (bRow + 16) * ROWH + ksub * 16 + bK) * 2;
                    ldm4(t, bd);
                    b1[2][0] = t[0]; b1[2][1] = t[1];
                    b1[3][0] = t[2]; b1[3][1] = t[3];
                }
#pragma unroll
                for (int im = 0; im < 2; im++)
#pragma unroll
                    for (int jn = 0; jn < 4; jn++) {
                        mma_acc(al[im][jn], a0[ks][im], b1[jn]);  // h * l'
                        mma_acc(al[im][jn], a1[im], b0[ks][jn]);  // l' * h
                    }
            }
        }
        // all warps finished reading stage s; now its buffer may be refilled
        __syncthreads();
        if (s + 2 < NCH) fill(s & 1, s + 2);
    }

    // fold scaled cross-term accumulator, store
#pragma unroll
    for (int im = 0; im < 2; im++) {
#pragma unroll
        for (int jn = 0; jn < 4; jn++) {
#pragma unroll
            for (int q = 0; q < 4; q++)
                ct[im][jn][q] = fmaf(al[im][jn][q], LINV, ct[im][jn][q]);
            int row = m0 + wm * 32 + im * 16 + r4;
            int col = n0 + wn * 32 + jn * 8 + cq * 2;
            *(float2*)&g_lin[(size_t)row * D2 + col] =
                make_float2(ct[im][jn][0], ct[im][jn][1]);
            *(float2*)&g_lin[(size_t)(row + 8) * D2 + col] =
                make_float2(ct[im][jn][2], ct[im][jn][3]);
        }
    }
}

// ---------------------------------------------------------------------------
// LIF scan: one thread per float2, prefetch depth 2 (MLP=2 per thread).
// FP arithmetic order unchanged from the verified 5.2549e-4 variant.
// ---------------------------------------------------------------------------
__global__ __launch_bounds__(256, 8) void scan_kernel(float* __restrict__ out) {
    const float ALPHA = 0.7788007830714049f;  // exp(-1/4)
    const float BETA  = 0.9512294245007140f;  // exp(-1/20)

    int j = blockIdx.x * blockDim.x + threadIdx.x;

    const float2* lin = (const float2*)g_lin;
    float2* spk = (float2*)out;
    float2* V   = spk + TOTAL2;
    float2* I   = V + TOTAL2;

    float sx = 0.f, sy = 0.f, mx = 0.f, my = 0.f;

    float2 z = make_float2(0.f, 0.f);
    spk[j] = z; V[j] = z; I[j] = z;

    // depth-2 prefetch: cur = lin[t-1], nxt = lin[t], fut issued 2 iters ahead
    float2 cur = lin[j];                  // lin[0]
    float2 nxt = lin[(size_t)PLANE2 + j]; // lin[1]

#pragma unroll 1
    for (int t = 1; t < STEPS; t++) {
        float2 fut = nxt;
        if (t <= STEPS - 3) fut = lin[(size_t)(t + 1) * PLANE2 + j];  // lin[t+1]

        float kx = (mx > 1.0f) ? 0.0f : 1.0f;
        float ky = (my > 1.0f) ? 0.0f : 1.0f;

        sx = ALPHA * sx + cur.x;
        sy = ALPHA * sy + cur.y;
        mx = (BETA * mx + sx) * kx;
        my = (BETA * my + sy) * ky;

        float2 o;
        o.x = (mx > 1.0f) ? 1.0f : 0.0f;
        o.y = (my > 1.0f) ? 1.0f : 0.0f;

        size_t off = (size_t)t * PLANE2 + j;
        spk[off] = o;
        V[off]   = make_float2(mx, my);
        I[off]   = make_float2(sx, sy);

        cur = nxt;
        nxt = fut;
    }
}

// ---------------------------------------------------------------------------
extern "C" void kernel_launch(void* const* d_in, const int* in_sizes, int n_in,
                              void* d_out, int out_size) {
    const float* input  = (const float*)d_in[0];   // [128, 256, 1024]
    const float* weight = (const float*)d_in[1];   // [1024, 1024]
    float* out = (float*)d_out;                    // [3, 128, 256, 1024]

    __half *pA, *pW;
    cudaGetSymbolAddress((void**)&pA, g_A);
    cudaGetSymbolAddress((void**)&pW, g_W);
    const size_t APL = (size_t)M_ROWS * D1;
    const size_t WPL = (size_t)D2 * D1;

    int nA8 = (M_ROWS * D1) / 8;
    int nW8 = (D2 * D1) / 8;
    split2<<<(nA8 + 255) / 256, 256>>>(input, pA, pA + APL, nA8);
    split2<<<(nW8 + 255) / 256, 256>>>(weight, pW, pW + WPL, nW8);

    cudaFuncSetAttribute(gemm_limb_kernel, cudaFuncAttributeMaxDynamicSharedMemorySize, SMEM_BYTES);
    gemm_limb_kernel<<<dim3(D2 / 64, M_ROWS / 128), 256, SMEM_BYTES>>>();

    scan_kernel<<<PLANE2 / 256, 256>>>(out);
}

// round 17
// speedup vs baseline: 1.0007x; 1.0007x over previous
#include <cuda_runtime.h>
#include <cuda_fp16.h>
#include <cstdint>

// ---------------------------------------------------------------------------
// Problem constants
// ---------------------------------------------------------------------------
#define STEPS 128
#define BATCH 256
#define D1 1024
#define D2 1024
#define M_ROWS (127 * BATCH)        // 32512
#define PLANE (BATCH * D2)          // 262144
#define PLANE2 (PLANE / 2)
#define TOTAL2 (STEPS * PLANE2)

#define LSCALE 2048.0f              // 2^11 lo-limb scaling (kills subnormals)
#define LINV   (1.0f / 2048.0f)

// GEMM tiling: CTA 128(M) x 64(N), K-chunk 64, 256 threads (8 warps 4x2),
// 2-stage pipeline, 2 CTAs per SM.  (Best-measured config: R10/R15, 682.5 us.)
#define KC 64
#define NCH 16                      // 1024 / 64 chunks
#define ROWH 72                     // 64 data halfs + 8 pad
#define TA_H (128 * ROWH)           // 9216 halfs per A limb tile
#define TB_H (64 * ROWH)            // 4608 halfs per W limb tile
#define WOFF_H (2 * TA_H)           // W tiles after the 2 A tiles
#define STAGE_H (2 * TA_H + 2 * TB_H)  // 27648 halfs
#define STAGE_B (STAGE_H * 2)       // 55296 bytes
#define SMEM_BYTES (2 * STAGE_B)    // 110592 bytes -> 2 CTAs/SM

// ---------------------------------------------------------------------------
// Device scratch
// ---------------------------------------------------------------------------
__device__ float  g_lin[(size_t)M_ROWS * D2];     // 133 MB
__device__ __half g_A[2][(size_t)M_ROWS * D1];    // 2 x 66.6 MB
__device__ __half g_W[2][(size_t)D2 * D1];        // 2 x 2 MB

// ---------------------------------------------------------------------------
// 2-limb fp16 split with scaled lo: x ~= h + l*2^-11,  l = f16((x-h)*2^11)
// ---------------------------------------------------------------------------
__global__ __launch_bounds__(256) void split2(const float* __restrict__ src,
                                              __half* __restrict__ oh,
                                              __half* __restrict__ ol, int n8) {
    int i = blockIdx.x * blockDim.x + threadIdx.x;
    if (i >= n8) return;
    const float4* s = (const float4*)(src + (size_t)i * 8);
    float4 v0 = s[0], v1 = s[1];
    float x[8] = {v0.x, v0.y, v0.z, v0.w, v1.x, v1.y, v1.z, v1.w};
    unsigned short h[8], l[8];
#pragma unroll
    for (int q = 0; q < 8; q++) {
        __half a = __float2half_rn(x[q]);
        float r = (x[q] - __half2float(a)) * LSCALE;
        h[q] = __half_as_ushort(a);
        l[q] = __half_as_ushort(__float2half_rn(r));
    }
    uint4 p;
    p.x = h[0] | ((uint32_t)h[1] << 16); p.y = h[2] | ((uint32_t)h[3] << 16);
    p.z = h[4] | ((uint32_t)h[5] << 16); p.w = h[6] | ((uint32_t)h[7] << 16);
    ((uint4*)oh)[i] = p;
    p.x = l[0] | ((uint32_t)l[1] << 16); p.y = l[2] | ((uint32_t)l[3] << 16);
    p.z = l[4] | ((uint32_t)l[5] << 16); p.w = l[6] | ((uint32_t)l[7] << 16);
    ((uint4*)ol)[i] = p;
}

// ---------------------------------------------------------------------------
// MMA / ldmatrix helpers (fp16, fp32 accumulate)
// ---------------------------------------------------------------------------
__device__ __forceinline__ void ldm4(uint32_t* r, uint32_t a) {
    asm volatile("ldmatrix.sync.aligned.m8n8.x4.shared.b16 {%0,%1,%2,%3}, [%4];"
        : "=r"(r[0]), "=r"(r[1]), "=r"(r[2]), "=r"(r[3]) : "r"(a));
}
__device__ __forceinline__ void mma_acc(float* c, const uint32_t* a, const uint32_t* b) {
    asm volatile(
        "mma.sync.aligned.m16n8k16.row.col.f32.f16.f16.f32 "
        "{%0,%1,%2,%3}, {%4,%5,%6,%7}, {%8,%9}, {%0,%1,%2,%3};"
        : "+f"(c[0]), "+f"(c[1]), "+f"(c[2]), "+f"(c[3])
        : "r"(a[0]), "r"(a[1]), "r"(a[2]), "r"(a[3]), "r"(b[0]), "r"(b[1]));
}
__device__ __forceinline__ void mma_zro(float* d, const uint32_t* a, const uint32_t* b) {
    asm volatile(
        "mma.sync.aligned.m16n8k16.row.col.f32.f16.f16.f32 "
        "{%0,%1,%2,%3}, {%4,%5,%6,%7}, {%8,%9}, {%10,%10,%10,%10};"
        : "=f"(d[0]), "=f"(d[1]), "=f"(d[2]), "=f"(d[3])
        : "r"(a[0]), "r"(a[1]), "r"(a[2]), "r"(a[3]), "r"(b[0]), "r"(b[1]),
          "f"(0.0f));
}

// ---------------------------------------------------------------------------
// GEMM: lin = A @ W^T via 3 fp16 limb products.
// hh: chain length 2 (one k32 pair per fresh chain) then RN FADD into ct --
// empirically-validated anti-RZ scheme. Cross (h*l' + l'*h): chained in al at
// 2^11 scale; ct += al * 2^-11 at the end. ll dropped (<= 2^-24 relative).
// CTA 128x64, 256 thr, 2-stage cp.async pipeline (2-barrier schedule),
// 2 CTAs/SM so one CTA's HMMAs cover the other's barrier drains.
// ---------------------------------------------------------------------------
__global__ __launch_bounds__(256, 2) void gemm_limb_kernel() {
    extern __shared__ __half smp[];
    const int tid = threadIdx.x, lane = tid & 31, wid = tid >> 5;
    const int wm = wid & 3, wn = wid >> 2;       // 4(M) x 2(N) warp grid
    const int r4 = lane >> 2, cq = lane & 3;
    const int nb = blockIdx.x, mb = blockIdx.y;
    const int m0 = mb * 128, n0 = nb * 64;
    uint32_t smem_base = (uint32_t)__cvta_generic_to_shared(smp);

    float ct[2][4][4], al[2][4][4];
#pragma unroll
    for (int im = 0; im < 2; im++)
#pragma unroll
        for (int jn = 0; jn < 4; jn++)
#pragma unroll
            for (int q = 0; q < 4; q++) { ct[im][jn][q] = 0.f; al[im][jn][q] = 0.f; }

    const __half* Ab = &g_A[0][0] + (size_t)m0 * D1;
    const __half* Wb = &g_W[0][0] + (size_t)n0 * D1;
    const size_t APL = (size_t)M_ROWS * D1;
    const size_t WPL = (size_t)D2 * D1;

    // fill one stage: A 2x128 rows + W 2x64 rows, 8x16B per row -> 3072 chunks
    auto fill = [&](int buf, int kc) {
        int k0 = kc * KC;
        uint32_t sb = smem_base + (uint32_t)buf * STAGE_B;
#pragma unroll
        for (int i = 0; i < 8; i++) {            // A: 2048 chunks
            int ch = i * 256 + tid;
            int tile = ch >> 10;                 // 0=Ah 1=Al
            int r = (ch >> 3) & 127;
            int q = ch & 7;
            const void* src = Ab + (size_t)tile * APL + (size_t)r * D1 + k0 + q * 8;
            uint32_t dst = sb + (uint32_t)(tile * TA_H + r * ROWH + q * 8) * 2;
            asm volatile("cp.async.cg.shared.global [%0], [%1], 16;" :: "r"(dst), "l"(src));
        }
#pragma unroll
        for (int i = 0; i < 4; i++) {            // W: 1024 chunks
            int ch = i * 256 + tid;
            int tile = ch >> 9;                  // 0=Wh 1=Wl
            int r = (ch >> 3) & 63;
            int q = ch & 7;
            const void* src = Wb + (size_t)tile * WPL + (size_t)r * D1 + k0 + q * 8;
            uint32_t dst = sb + (uint32_t)(WOFF_H + tile * TB_H + r * ROWH + q * 8) * 2;
            asm volatile("cp.async.cg.shared.global [%0], [%1], 16;" :: "r"(dst), "l"(src));
        }
        asm volatile("cp.async.commit_group;");
    };

    fill(0, 0);
    fill(1, 1);

    // ldmatrix per-lane address components (halfs) — verified mapping
    const int aRow = wm * 32 + (lane & 15);
    const int aK   = (lane >> 4) * 8;
    const int bRow = wn * 32 + (lane >> 4) * 8 + (lane & 7);
    const int bK   = ((lane >> 3) & 1) * 8;

    for (int s = 0; s < NCH; s++) {
        // fill(s) must be complete: pending groups are fill(s), fill(s+1)
        if (s < NCH - 1) asm volatile("cp.async.wait_group 1;");
        else             asm volatile("cp.async.wait_group 0;");
        __syncthreads();                          // make fill(s) visible to all

        uint32_t sb = smem_base + (uint32_t)(s & 1) * STAGE_B;
#pragma unroll
        for (int kp = 0; kp < 2; kp++) {          // pairs of k16 steps
            uint32_t a0[2][2][4];                 // [ks][im]
            uint32_t b0[2][4][2];                 // [ks][jn]
#pragma unroll
            for (int ks = 0; ks < 2; ks++) {
                int ksub = kp * 2 + ks;
#pragma unroll
                for (int im = 0; im < 2; im++) {
                    uint32_t ad = sb + (uint32_t)((aRow + im * 16) * ROWH
                                   + ksub * 16 + aK) * 2;
                    ldm4(a0[ks][im], ad);
                }
                {
                    uint32_t bd = sb + (uint32_t)(WOFF_H
                                   + bRow * ROWH + ksub * 16 + bK) * 2;
                    uint32_t t[4];
                    ldm4(t, bd);
                    b0[ks][0][0] = t[0]; b0[ks][0][1] = t[1];
                    b0[ks][1][0] = t[2]; b0[ks][1][1] = t[3];
                    bd = sb + (uint32_t)(WOFF_H
                         + (bRow + 16) * ROWH + ksub * 16 + bK) * 2;
                    ldm4(t, bd);
                    b0[ks][2][0] = t[0]; b0[ks][2][1] = t[1];
                    b0[ks][3][0] = t[2]; b0[ks][3][1] = t[3];
                }
            }
            // hh: fresh chain over the k32 pair, then RN dump
#pragma unroll
            for (int im = 0; im < 2; im++)
#pragma unroll
                for (int jn = 0; jn < 4; jn++) {
                    float t4[4];
                    mma_zro(t4, a0[0][im], b0[0][jn]);
                    mma_acc(t4, a0[1][im], b0[1][jn]);
#pragma unroll
                    for (int q = 0; q < 4; q++) ct[im][jn][q] += t4[q];
                }
            // cross terms per k16 (lo-limb frags transient)
#pragma unroll
            for (int ks = 0; ks < 2; ks++) {
                int ksub = kp * 2 + ks;
                uint32_t a1[2][4], b1[4][2];
#pragma unroll
                for (int im = 0; im < 2; im++) {
                    uint32_t ad = sb + (uint32_t)(TA_H + (aRow + im * 16) * ROWH
                                   + ksub * 16 + aK) * 2;
                    ldm4(a1[im], ad);
                }
                {
                    uint32_t bd = sb + (uint32_t)(WOFF_H + TB_H
                                   + bRow * ROWH + ksub * 16 + bK) * 2;
                    uint32_t t[4];
                    ldm4(t, bd);
                    b1[0][0] = t[0]; b1[0][1] = t[1];
                    b1[1][0] = t[2]; b1[1][1] = t[3];
                    bd = sb + (uint32_t)(WOFF_H + TB_H
                         + (bRow + 16) * ROWH + ksub * 16 + bK) * 2;
                    ldm4(t, bd);
                    b1[2][0] = t[0]; b1[2][1] = t[1];
                    b1[3][0] = t[2]; b1[3][1] = t[3];
                }
#pragma unroll
                for (int im = 0; im < 2; im++)
#pragma unroll
                    for (int jn = 0; jn < 4; jn++) {
                        mma_acc(al[im][jn], a0[ks][im], b1[jn]);  // h * l'
                        mma_acc(al[im][jn], a1[im], b0[ks][jn]);  // l' * h
                    }
            }
        }
        // all warps finished reading stage s; now its buffer may be refilled
        __syncthreads();
        if (s + 2 < NCH) fill(s & 1, s + 2);
    }

    // fold scaled cross-term accumulator, store
#pragma unroll
    for (int im = 0; im < 2; im++) {
#pragma unroll
        for (int jn = 0; jn < 4; jn++) {
#pragma unroll
            for (int q = 0; q < 4; q++)
                ct[im][jn][q] = fmaf(al[im][jn][q], LINV, ct[im][jn][q]);
            int row = m0 + wm * 32 + im * 16 + r4;
            int col = n0 + wn * 32 + jn * 8 + cq * 2;
            *(float2*)&g_lin[(size_t)row * D2 + col] =
                make_float2(ct[im][jn][0], ct[im][jn][1]);
            *(float2*)&g_lin[(size_t)(row + 8) * D2 + col] =
                make_float2(ct[im][jn][2], ct[im][jn][3]);
        }
    }
}

// ---------------------------------------------------------------------------
// LIF scan: one thread per float2, prefetch depth 2 (MLP=2 per thread).
// FP arithmetic order unchanged from the verified 5.2549e-4 variant.
// ---------------------------------------------------------------------------
__global__ __launch_bounds__(256, 8) void scan_kernel(float* __restrict__ out) {
    const float ALPHA = 0.7788007830714049f;  // exp(-1/4)
    const float BETA  = 0.9512294245007140f;  // exp(-1/20)

    int j = blockIdx.x * blockDim.x + threadIdx.x;

    const float2* lin = (const float2*)g_lin;
    float2* spk = (float2*)out;
    float2* V   = spk + TOTAL2;
    float2* I   = V + TOTAL2;

    float sx = 0.f, sy = 0.f, mx = 0.f, my = 0.f;

    float2 z = make_float2(0.f, 0.f);
    spk[j] = z; V[j] = z; I[j] = z;

    // depth-2 prefetch: cur = lin[t-1], nxt = lin[t], fut issued 2 iters ahead
    float2 cur = lin[j];                  // lin[0]
    float2 nxt = lin[(size_t)PLANE2 + j]; // lin[1]

#pragma unroll 1
    for (int t = 1; t < STEPS; t++) {
        float2 fut = nxt;
        if (t <= STEPS - 3) fut = lin[(size_t)(t + 1) * PLANE2 + j];  // lin[t+1]

        float kx = (mx > 1.0f) ? 0.0f : 1.0f;
        float ky = (my > 1.0f) ? 0.0f : 1.0f;

        sx = ALPHA * sx + cur.x;
        sy = ALPHA * sy + cur.y;
        mx = (BETA * mx + sx) * kx;
        my = (BETA * my + sy) * ky;

        float2 o;
        o.x = (mx > 1.0f) ? 1.0f : 0.0f;
        o.y = (my > 1.0f) ? 1.0f : 0.0f;

        size_t off = (size_t)t * PLANE2 + j;
        spk[off] = o;
        V[off]   = make_float2(mx, my);
        I[off]   = make_float2(sx, sy);

        cur = nxt;
        nxt = fut;
    }
}

// ---------------------------------------------------------------------------
extern "C" void kernel_launch(void* const* d_in, const int* in_sizes, int n_in,
                              void* d_out, int out_size) {
    const float* input  = (const float*)d_in[0];   // [128, 256, 1024]
    const float* weight = (const float*)d_in[1];   // [1024, 1024]
    float* out = (float*)d_out;                    // [3, 128, 256, 1024]

    __half *pA, *pW;
    cudaGetSymbolAddress((void**)&pA, g_A);
    cudaGetSymbolAddress((void**)&pW, g_W);
    const size_t APL = (size_t)M_ROWS * D1;
    const size_t WPL = (size_t)D2 * D1;

    int nA8 = (M_ROWS * D1) / 8;
    int nW8 = (D2 * D1) / 8;
    split2<<<(nA8 + 255) / 256, 256>>>(input, pA, pA + APL, nA8);
    split2<<<(nW8 + 255) / 256, 256>>>(weight, pW, pW + WPL, nW8);

    cudaFuncSetAttribute(gemm_limb_kernel, cudaFuncAttributeMaxDynamicSharedMemorySize, SMEM_BYTES);
    gemm_limb_kernel<<<dim3(D2 / 64, M_ROWS / 128), 256, SMEM_BYTES>>>();

    scan_kernel<<<PLANE2 / 256, 256>>>(out);
}